// round 1
// baseline (speedup 1.0000x reference)
#include <cuda_runtime.h>
#include <cuda_bf16.h>
#include <mma.h>

using namespace nvcuda;

#define N_OBS 2048
#define KH    1024
#define DIN   64

// Scratch (device globals: allocation-free per harness rules)
__device__ float g_s[N_OBS * KH];   // 8 MB: sin(z), (n, K) row-major
__device__ float g_M[KH * KH];      // 4 MB: Gram of sin-activations, scaled

// ---------------------------------------------------------------------------
// Kernel A: s[n][k] = sinf( dot(x[n,:], w[k,:]) + b[k] )
// grid = N_OBS/16 blocks, 256 threads. Stage x tile + transposed w chunk in smem.
// ---------------------------------------------------------------------------
#define A_NT 16
#define A_KC 128
#define A_WPAD 132   // row pad (132 % 32 == 4) -> 4-way staging conflicts, f4-aligned

__global__ void __launch_bounds__(256) kernelA(const float* __restrict__ x,
                                               const float* __restrict__ w,
                                               const float* __restrict__ b) {
    __shared__ float xs[A_NT][DIN];        // 4 KB
    __shared__ float wsT[DIN][A_WPAD];     // 33.8 KB  (wsT[d][k_local])

    const int tid = threadIdx.x;
    const int n0  = blockIdx.x * A_NT;

    // stage x tile (coalesced)
    for (int i = tid; i < A_NT * DIN; i += 256) {
        xs[i >> 6][i & 63] = x[(n0 + (i >> 6)) * DIN + (i & 63)];
    }

    const int lane4 = (tid & 31) * 4;   // k_local base (4 consecutive k per lane)
    const int nn    = tid >> 5;         // warp id -> 2 n rows

    for (int kc = 0; kc < KH; kc += A_KC) {
        __syncthreads();   // protect wsT reuse + xs first use
        // stage w chunk transposed: wsT[d][k] = w[(kc+k)*DIN + d]  (coalesced global)
        for (int i = tid; i < A_KC * DIN; i += 256) {
            const int k = i >> 6, d = i & 63;
            wsT[d][k] = w[(kc + k) * DIN + d];
        }
        __syncthreads();

        float a00 = 0.f, a01 = 0.f, a02 = 0.f, a03 = 0.f;
        float a10 = 0.f, a11 = 0.f, a12 = 0.f, a13 = 0.f;

        #pragma unroll 16
        for (int d = 0; d < DIN; d++) {
            const float4 wv = *(const float4*)&wsT[d][lane4];  // LDS.128, conflict-free
            const float x0 = xs[2 * nn][d];                    // broadcast
            const float x1 = xs[2 * nn + 1][d];
            a00 += x0 * wv.x; a01 += x0 * wv.y; a02 += x0 * wv.z; a03 += x0 * wv.w;
            a10 += x1 * wv.x; a11 += x1 * wv.y; a12 += x1 * wv.z; a13 += x1 * wv.w;
        }

        const float4 bb = *(const float4*)&b[kc + lane4];
        float4 o0, o1;
        o0.x = sinf(a00 + bb.x); o0.y = sinf(a01 + bb.y);
        o0.z = sinf(a02 + bb.z); o0.w = sinf(a03 + bb.w);
        o1.x = sinf(a10 + bb.x); o1.y = sinf(a11 + bb.y);
        o1.z = sinf(a12 + bb.z); o1.w = sinf(a13 + bb.w);

        *(float4*)&g_s[(size_t)(n0 + 2 * nn)     * KH + kc + lane4] = o0;
        *(float4*)&g_s[(size_t)(n0 + 2 * nn + 1) * KH + kc + lane4] = o1;
    }
}

// ---------------------------------------------------------------------------
// Kernel B: M = (2/K/n) * s^T s   via wmma tf32 m16n16k8
// grid = (8, 8) CTAs of 128x128 tiles, 256 threads (8 warps, 4x2 warp grid,
// warp tile 32x64 = 2x4 wmma tiles). K-chunks of 32 n staged in smem.
// ---------------------------------------------------------------------------
#define B_KC 32

__global__ void __launch_bounds__(256) kernelB() {
    __shared__ float sA[B_KC][128];   // sA[n][i_local]
    __shared__ float sB[B_KC][128];   // sB[n][l_local]

    const int tid = threadIdx.x;
    const int l0  = blockIdx.x * 128;
    const int i0  = blockIdx.y * 128;
    const int warpId = tid >> 5;
    const int wr = warpId & 3;   // -> i offset wr*32
    const int wc = warpId >> 2;  // -> l offset wc*64

    wmma::fragment<wmma::accumulator, 16, 16, 8, float> acc[2][4];
    #pragma unroll
    for (int ti = 0; ti < 2; ti++)
        #pragma unroll
        for (int tj = 0; tj < 4; tj++)
            wmma::fill_fragment(acc[ti][tj], 0.0f);

    for (int nc = 0; nc < N_OBS; nc += B_KC) {
        __syncthreads();
        for (int i = tid; i < B_KC * 128; i += 256) {
            const int r = i >> 7, c = i & 127;
            sA[r][c] = g_s[(size_t)(nc + r) * KH + i0 + c];
            sB[r][c] = g_s[(size_t)(nc + r) * KH + l0 + c];
        }
        __syncthreads();

        #pragma unroll
        for (int ks = 0; ks < B_KC; ks += 8) {
            wmma::fragment<wmma::matrix_a, 16, 16, 8, wmma::precision::tf32, wmma::col_major> af[2];
            wmma::fragment<wmma::matrix_b, 16, 16, 8, wmma::precision::tf32, wmma::row_major> bf[4];
            #pragma unroll
            for (int ti = 0; ti < 2; ti++) {
                // A(i, n) lives at sA[n][i]: col-major, ld = 128
                wmma::load_matrix_sync(af[ti], &sA[ks][wr * 32 + ti * 16], 128);
                #pragma unroll
                for (int t = 0; t < af[ti].num_elements; t++)
                    af[ti].x[t] = wmma::__float_to_tf32(af[ti].x[t]);
            }
            #pragma unroll
            for (int tj = 0; tj < 4; tj++) {
                // B(n, l) lives at sB[n][l]: row-major, ld = 128
                wmma::load_matrix_sync(bf[tj], &sB[ks][wc * 64 + tj * 16], 128);
                #pragma unroll
                for (int t = 0; t < bf[tj].num_elements; t++)
                    bf[tj].x[t] = wmma::__float_to_tf32(bf[tj].x[t]);
            }
            #pragma unroll
            for (int ti = 0; ti < 2; ti++)
                #pragma unroll
                for (int tj = 0; tj < 4; tj++)
                    wmma::mma_sync(acc[ti][tj], af[ti], bf[tj], acc[ti][tj]);
        }
    }

    const float sc = (2.0f / (float)KH) / (float)N_OBS;  // fold scale^2 / n
    #pragma unroll
    for (int ti = 0; ti < 2; ti++)
        #pragma unroll
        for (int tj = 0; tj < 4; tj++) {
            #pragma unroll
            for (int t = 0; t < acc[ti][tj].num_elements; t++)
                acc[ti][tj].x[t] *= sc;
            wmma::store_matrix_sync(
                &g_M[(size_t)(i0 + wr * 32 + ti * 16) * KH + l0 + wc * 64 + tj * 16],
                acc[ti][tj], KH, wmma::mem_row_major);
        }
}

// ---------------------------------------------------------------------------
// Kernel C: A[d,k,l] = M[k,l] * w[k,d] * w[l,d]
// grid = (K/128 l-tiles, K/8 k-tiles), 256 threads. 256 MB store-bound.
// M held in registers across the d loop; w l-slice staged transposed in smem.
// ---------------------------------------------------------------------------
#define C_KT 8
#define C_LT 128
#define C_WPAD 132

__global__ void __launch_bounds__(256) kernelC(const float* __restrict__ w,
                                               float* __restrict__ out) {
    __shared__ float wld[DIN][C_WPAD];   // wld[d][l_local]  33.8 KB
    __shared__ float Ms[C_KT][C_LT];     // 4 KB
    __shared__ float wks[DIN][C_KT + 1]; // 2.25 KB (pad -> conflict-free)

    const int tid = threadIdx.x;
    const int l0  = blockIdx.x * C_LT;
    const int k0  = blockIdx.y * C_KT;

    for (int i = tid; i < DIN * C_LT; i += 256) {
        const int li = i >> 6, d = i & 63;
        wld[d][li] = w[(size_t)(l0 + li) * DIN + d];     // coalesced global read
    }
    for (int i = tid; i < C_KT * C_LT; i += 256) {
        const int kk = i >> 7, li = i & 127;
        Ms[kk][li] = g_M[(size_t)(k0 + kk) * KH + l0 + li];
    }
    for (int i = tid; i < C_KT * DIN; i += 256) {
        const int kk = i >> 6, d = i & 63;
        wks[d][kk] = w[(size_t)(k0 + kk) * DIN + d];
    }
    __syncthreads();

    const int j     = tid >> 5;          // warp -> kk
    const int lane4 = (tid & 31) * 4;    // 4 consecutive l per lane
    const float4 M4 = *(const float4*)&Ms[j][lane4];
    const size_t base = (size_t)(k0 + j) * KH + l0 + lane4;

    #pragma unroll 8
    for (int d = 0; d < DIN; d++) {
        const float wk  = wks[d][j];                        // broadcast
        const float4 wl = *(const float4*)&wld[d][lane4];   // LDS.128
        float4 o;
        o.x = (M4.x * wk) * wl.x;
        o.y = (M4.y * wk) * wl.y;
        o.z = (M4.z * wk) * wl.z;
        o.w = (M4.w * wk) * wl.w;
        *(float4*)&out[(size_t)d * (size_t)(KH * KH) + base] = o;  // STG.128, contiguous/warp
    }
}

// ---------------------------------------------------------------------------
extern "C" void kernel_launch(void* const* d_in, const int* in_sizes, int n_in,
                              void* d_out, int out_size) {
    (void)in_sizes; (void)n_in; (void)out_size;
    const float* x = (const float*)d_in[0];
    const float* w = (const float*)d_in[1];
    const float* b = (const float*)d_in[2];
    float* out = (float*)d_out;

    kernelA<<<N_OBS / A_NT, 256>>>(x, w, b);
    kernelB<<<dim3(KH / 128, KH / 128), 256>>>();
    kernelC<<<dim3(KH / C_LT, KH / C_KT), 256>>>(w, out);
}

// round 2
// speedup vs baseline: 2.5997x; 2.5997x over previous
#include <cuda_runtime.h>
#include <cuda_bf16.h>
#include <mma.h>

using namespace nvcuda;

#define N_OBS 2048
#define KH    1024
#define DIN   64
#define NTILE 8          // KH / 128
#define NPAIR 36         // upper-triangle tile pairs
#define NSPLIT 8         // split-K factor for kernelB

// Scratch (device globals: allocation-free per harness rules)
__device__ float g_s[N_OBS * KH];                        // 8 MB: sin activations (n, K)
__device__ float g_M[KH * KH];                           // 4 MB: full symmetric Gram
__device__ float g_Mp[NSPLIT * NPAIR * 128 * 128];       // 18 MB: per-(split,tile) partials

// map upper-triangle pair index -> (tr, tc), tr <= tc
__device__ __forceinline__ void pair_from_idx(int idx, int& tr, int& tc) {
    int t = 0, rem = idx;
    while (rem >= NTILE - t) { rem -= NTILE - t; t++; }
    tr = t; tc = t + rem;
}

// ---------------------------------------------------------------------------
// Kernel A: s[n][k] = sinf( dot(x[n,:], w[k,:]) + b[k] )
// grid = (KH/128, N_OBS/32), 256 threads. Warp handles 4 n-rows x 128 k.
// ---------------------------------------------------------------------------
#define A_NT 32
#define A_KC 128
#define A_WPAD 132   // % 32 == 4 (4-way staging conflicts only), float4-aligned

__global__ void __launch_bounds__(256) kernelA(const float* __restrict__ x,
                                               const float* __restrict__ w,
                                               const float* __restrict__ b) {
    __shared__ float xs[A_NT][DIN];        // 8 KB
    __shared__ float wsT[DIN][A_WPAD];     // 33.8 KB  wsT[d][k_local]

    const int tid = threadIdx.x;
    const int kc  = blockIdx.x * A_KC;
    const int n0  = blockIdx.y * A_NT;

    // stage x tile (coalesced)
    for (int i = tid; i < A_NT * DIN; i += 256)
        xs[i >> 6][i & 63] = x[(size_t)(n0 + (i >> 6)) * DIN + (i & 63)];
    // stage w chunk transposed (coalesced global reads)
    for (int i = tid; i < A_KC * DIN; i += 256) {
        const int k = i >> 6, d = i & 63;
        wsT[d][k] = w[(size_t)(kc + k) * DIN + d];
    }
    __syncthreads();

    const int warp  = tid >> 5;
    const int lane4 = (tid & 31) * 4;
    const int r0 = warp * 4;

    float acc[4][4];
    #pragma unroll
    for (int r = 0; r < 4; r++)
        #pragma unroll
        for (int c = 0; c < 4; c++) acc[r][c] = 0.f;

    #pragma unroll 8
    for (int d = 0; d < DIN; d++) {
        const float4 wv = *(const float4*)&wsT[d][lane4];  // LDS.128 conflict-free
        #pragma unroll
        for (int r = 0; r < 4; r++) {
            const float xv = xs[r0 + r][d];                // broadcast
            acc[r][0] += xv * wv.x; acc[r][1] += xv * wv.y;
            acc[r][2] += xv * wv.z; acc[r][3] += xv * wv.w;
        }
    }

    const float4 bb = *(const float4*)&b[kc + lane4];
    #pragma unroll
    for (int r = 0; r < 4; r++) {
        float4 o;
        o.x = sinf(acc[r][0] + bb.x);
        o.y = sinf(acc[r][1] + bb.y);
        o.z = sinf(acc[r][2] + bb.z);
        o.w = sinf(acc[r][3] + bb.w);
        *(float4*)&g_s[(size_t)(n0 + r0 + r) * KH + kc + lane4] = o;
    }
}

// ---------------------------------------------------------------------------
// Kernel B: partial Gram  Mp[split,tile] = sc * s[ns]^T s[ns]  (tf32 wmma)
// grid = (36 upper tiles, 8 splits), 256 threads, 128x128 tile, K-chunk 32.
// ---------------------------------------------------------------------------
#define B_KC  32
#define B_LD  132    // multiple of 4 (wmma ldm requirement), breaks 32-way conflicts

__global__ void __launch_bounds__(256) kernelB() {
    __shared__ float sA[B_KC][B_LD];
    __shared__ float sB[B_KC][B_LD];

    const int tid = threadIdx.x;
    int tr, tc; pair_from_idx(blockIdx.x, tr, tc);
    const int i0 = tr * 128;
    const int l0 = tc * 128;
    const int nbase = blockIdx.y * (N_OBS / NSPLIT);

    const int warpId = tid >> 5;
    const int wr = warpId & 3;    // i offset wr*32
    const int wc = warpId >> 2;   // l offset wc*64

    wmma::fragment<wmma::accumulator, 16, 16, 8, float> acc[2][4];
    #pragma unroll
    for (int fi = 0; fi < 2; fi++)
        #pragma unroll
        for (int fj = 0; fj < 4; fj++)
            wmma::fill_fragment(acc[fi][fj], 0.0f);

    for (int nc = 0; nc < N_OBS / NSPLIT; nc += B_KC) {
        __syncthreads();
        for (int i = tid; i < B_KC * 128; i += 256) {
            const int r = i >> 7, c = i & 127;
            const size_t row = (size_t)(nbase + nc + r) * KH;
            sA[r][c] = g_s[row + i0 + c];
            sB[r][c] = g_s[row + l0 + c];
        }
        __syncthreads();

        #pragma unroll
        for (int ks = 0; ks < B_KC; ks += 8) {
            wmma::fragment<wmma::matrix_a, 16, 16, 8, wmma::precision::tf32, wmma::col_major> af[2];
            wmma::fragment<wmma::matrix_b, 16, 16, 8, wmma::precision::tf32, wmma::row_major> bf[4];
            #pragma unroll
            for (int fi = 0; fi < 2; fi++) {
                wmma::load_matrix_sync(af[fi], &sA[ks][wr * 32 + fi * 16], B_LD);
                #pragma unroll
                for (int t = 0; t < af[fi].num_elements; t++)
                    af[fi].x[t] = wmma::__float_to_tf32(af[fi].x[t]);
            }
            #pragma unroll
            for (int fj = 0; fj < 4; fj++) {
                wmma::load_matrix_sync(bf[fj], &sB[ks][wc * 64 + fj * 16], B_LD);
                #pragma unroll
                for (int t = 0; t < bf[fj].num_elements; t++)
                    bf[fj].x[t] = wmma::__float_to_tf32(bf[fj].x[t]);
            }
            #pragma unroll
            for (int fi = 0; fi < 2; fi++)
                #pragma unroll
                for (int fj = 0; fj < 4; fj++)
                    wmma::mma_sync(acc[fi][fj], af[fi], bf[fj], acc[fi][fj]);
        }
    }

    const float sc = (2.0f / (float)KH) / (float)N_OBS;
    float* dst = &g_Mp[((size_t)blockIdx.y * NPAIR + blockIdx.x) * (128 * 128)];
    #pragma unroll
    for (int fi = 0; fi < 2; fi++)
        #pragma unroll
        for (int fj = 0; fj < 4; fj++) {
            #pragma unroll
            for (int t = 0; t < acc[fi][fj].num_elements; t++)
                acc[fi][fj].x[t] *= sc;
            wmma::store_matrix_sync(
                &dst[(size_t)(wr * 32 + fi * 16) * 128 + wc * 64 + fj * 16],
                acc[fi][fj], 128, wmma::mem_row_major);
        }
}

// ---------------------------------------------------------------------------
// Kernel R: reduce 8 split-partials, write M tile + mirrored tile.
// grid = 36 tiles * 4 row-quarters, 256 threads. smem-staged transpose.
// ---------------------------------------------------------------------------
__global__ void __launch_bounds__(256) kernelR() {
    __shared__ float ts[32][133];   // 133: odd stride -> conflict-free transpose read

    const int tid  = threadIdx.x;
    const int tile = blockIdx.x >> 2;
    const int q    = blockIdx.x & 3;
    int tr, tc; pair_from_idx(tile, tr, tc);
    const int i0 = tr * 128 + q * 32;   // k rows handled by this CTA
    const int l0 = tc * 128;

    // sum partials into smem (coalesced reads)
    for (int e = tid; e < 32 * 128; e += 256) {
        const int r = e >> 7, c = e & 127;
        float v = 0.f;
        #pragma unroll
        for (int s = 0; s < NSPLIT; s++)
            v += g_Mp[((size_t)s * NPAIR + tile) * (128 * 128) + (size_t)(q * 32 + r) * 128 + c];
        ts[r][c] = v;
    }
    __syncthreads();

    // normal write: M[i0+r][l0+c]  (coalesced)
    for (int e = tid; e < 32 * 128; e += 256) {
        const int r = e >> 7, c = e & 127;
        g_M[(size_t)(i0 + r) * KH + l0 + c] = ts[r][c];
    }
    // mirrored write: M[l0+lr][i0+kc] (coalesced 128B segments); skip on diagonal
    if (tr != tc) {
        for (int e = tid; e < 128 * 32; e += 256) {
            const int lr = e >> 5, kc = e & 31;
            g_M[(size_t)(l0 + lr) * KH + i0 + kc] = ts[kc][lr];
        }
    }
}

// ---------------------------------------------------------------------------
// Kernel C: A[d,k,l] = M[k,l] * w[k,d] * w[l,d]   (256 MB store-bound)
// grid = (KH/128 l-tiles, KH/8 k-tiles), 256 threads.
// ---------------------------------------------------------------------------
#define C_KT 8
#define C_LT 128
#define C_WPAD 132

__global__ void __launch_bounds__(256) kernelC(const float* __restrict__ w,
                                               float* __restrict__ out) {
    __shared__ float wld[DIN][C_WPAD];   // wld[d][l_local]
    __shared__ float Ms[C_KT][C_LT];
    __shared__ float wks[DIN][C_KT + 1];

    const int tid = threadIdx.x;
    const int l0  = blockIdx.x * C_LT;
    const int k0  = blockIdx.y * C_KT;

    for (int i = tid; i < DIN * C_LT; i += 256) {
        const int li = i >> 6, d = i & 63;
        wld[d][li] = w[(size_t)(l0 + li) * DIN + d];
    }
    for (int i = tid; i < C_KT * C_LT; i += 256) {
        const int kk = i >> 7, li = i & 127;
        Ms[kk][li] = g_M[(size_t)(k0 + kk) * KH + l0 + li];
    }
    for (int i = tid; i < C_KT * DIN; i += 256) {
        const int kk = i >> 6, d = i & 63;
        wks[d][kk] = w[(size_t)(k0 + kk) * DIN + d];
    }
    __syncthreads();

    const int j     = tid >> 5;
    const int lane4 = (tid & 31) * 4;
    const float4 M4 = *(const float4*)&Ms[j][lane4];
    const size_t base = (size_t)(k0 + j) * KH + l0 + lane4;

    #pragma unroll 8
    for (int d = 0; d < DIN; d++) {
        const float wk  = wks[d][j];
        const float4 wl = *(const float4*)&wld[d][lane4];
        float4 o;
        o.x = (M4.x * wk) * wl.x;
        o.y = (M4.y * wk) * wl.y;
        o.z = (M4.z * wk) * wl.z;
        o.w = (M4.w * wk) * wl.w;
        *(float4*)&out[(size_t)d * (size_t)(KH * KH) + base] = o;
    }
}

// ---------------------------------------------------------------------------
extern "C" void kernel_launch(void* const* d_in, const int* in_sizes, int n_in,
                              void* d_out, int out_size) {
    (void)in_sizes; (void)n_in; (void)out_size;
    const float* x = (const float*)d_in[0];
    const float* w = (const float*)d_in[1];
    const float* b = (const float*)d_in[2];
    float* out = (float*)d_out;

    kernelA<<<dim3(KH / A_KC, N_OBS / A_NT), 256>>>(x, w, b);
    kernelB<<<dim3(NPAIR, NSPLIT), 256>>>();
    kernelR<<<NPAIR * 4, 256>>>();
    kernelC<<<dim3(KH / C_LT, KH / C_KT), 256>>>(w, out);
}

// round 4
// speedup vs baseline: 3.6427x; 1.4012x over previous
#include <cuda_runtime.h>
#include <cstdint>

#define N_OBS 2048
#define KH    1024
#define DIN   64
#define NTILE 8          // KH / 128
#define NPAIR 36         // upper-triangle tile pairs
#define NSPLIT 8         // split-K factor for kernelB

// Scratch (device globals: allocation-free per harness rules)
__device__ float g_sT[KH * N_OBS];                   // 8 MB: sin activations TRANSPOSED (k, n)
__device__ float g_M[KH * KH];                       // 4 MB: full symmetric Gram
__device__ float g_Mp[NSPLIT * NPAIR * 128 * 128];   // 18.9 MB: per-(split,tile) partials

// ---------------------------------------------------------------------------
// Helpers (all compute_103-portable: sm_80-class features only)
// ---------------------------------------------------------------------------
__device__ __forceinline__ void pair_from_idx(int idx, int& tr, int& tc) {
    int t = 0, rem = idx;
    while (rem >= NTILE - t) { rem -= NTILE - t; t++; }
    tr = t; tc = t + rem;
}
__device__ __forceinline__ float to_tf32(float x) {
    float y; asm("cvt.rna.tf32.f32 %0, %1;" : "=f"(y) : "f"(x)); return y;
}
__device__ __forceinline__ uint32_t smem_u32(const void* p) {
    uint32_t a;
    asm("{ .reg .u64 t; cvta.to.shared.u64 t, %1; cvt.u32.u64 %0, t; }" : "=r"(a) : "l"(p));
    return a;
}
__device__ __forceinline__ void cp_async16(uint32_t dst, const void* src) {
    asm volatile("cp.async.cg.shared.global [%0], [%1], 16;" :: "r"(dst), "l"(src));
}
#define CP_COMMIT() asm volatile("cp.async.commit_group;" ::: "memory")
#define CP_WAIT1()  asm volatile("cp.async.wait_group 1;" ::: "memory")
#define CP_WAIT0()  asm volatile("cp.async.wait_group 0;" ::: "memory")

// mma.sync m16n8k8 tf32, fp32 accumulate (raw bits in, no cvt in the hot loop)
__device__ __forceinline__ void mma_tf32(float* c, const uint32_t* a, const uint32_t* b) {
    asm volatile(
        "mma.sync.aligned.m16n8k8.row.col.f32.tf32.tf32.f32 "
        "{%0,%1,%2,%3}, {%4,%5,%6,%7}, {%8,%9}, {%0,%1,%2,%3};"
        : "+f"(c[0]), "+f"(c[1]), "+f"(c[2]), "+f"(c[3])
        : "r"(a[0]), "r"(a[1]), "r"(a[2]), "r"(a[3]), "r"(b[0]), "r"(b[1]));
}

// ---------------------------------------------------------------------------
// Kernel A: g_sT[k][n] = tf32( __sinf( dot(x[n,:], w[k,:]) + b[k] ) )
// grid = (KH/32, N_OBS/128), 256 threads. Warp: 4 k-rows x 128 n.
// ---------------------------------------------------------------------------
#define A_KT 32
#define A_NC 128
#define A_XPAD 132

__global__ void __launch_bounds__(256) kernelA(const float* __restrict__ x,
                                               const float* __restrict__ w,
                                               const float* __restrict__ b) {
    __shared__ float xsT[DIN][A_XPAD];      // 33.8 KB  xsT[d][n_local]
    __shared__ float wks[A_KT][DIN];        // 8 KB

    const int tid = threadIdx.x;
    const int k0  = blockIdx.x * A_KT;
    const int n0  = blockIdx.y * A_NC;

    for (int i = tid; i < A_NC * DIN; i += 256) {
        const int n = i >> 6, d = i & 63;
        xsT[d][n] = x[(size_t)(n0 + n) * DIN + d];      // coalesced read
    }
    for (int i = tid; i < A_KT * DIN; i += 256) {
        const int k = i >> 6, d = i & 63;
        wks[k][d] = w[(size_t)(k0 + k) * DIN + d];      // coalesced, conflict-free
    }
    __syncthreads();

    const int warp  = tid >> 5;
    const int lane4 = (tid & 31) * 4;
    const int r0 = warp * 4;

    float acc[4][4];
    #pragma unroll
    for (int r = 0; r < 4; r++)
        #pragma unroll
        for (int c = 0; c < 4; c++) acc[r][c] = 0.f;

    #pragma unroll 8
    for (int d = 0; d < DIN; d++) {
        const float4 xv = *(const float4*)&xsT[d][lane4];   // LDS.128 conflict-free
        #pragma unroll
        for (int r = 0; r < 4; r++) {
            const float wv = wks[r0 + r][d];                // broadcast
            acc[r][0] += wv * xv.x; acc[r][1] += wv * xv.y;
            acc[r][2] += wv * xv.z; acc[r][3] += wv * xv.w;
        }
    }

    #pragma unroll
    for (int r = 0; r < 4; r++) {
        const float bv = b[k0 + r0 + r];
        float4 o;
        o.x = to_tf32(__sinf(acc[r][0] + bv));
        o.y = to_tf32(__sinf(acc[r][1] + bv));
        o.z = to_tf32(__sinf(acc[r][2] + bv));
        o.w = to_tf32(__sinf(acc[r][3] + bv));
        *(float4*)&g_sT[(size_t)(k0 + r0 + r) * N_OBS + n0 + lane4] = o;
    }
}

// ---------------------------------------------------------------------------
// Kernel B: partial Gram Mp[split,pair][i][l] = sum_n sT[i][n] sT[l][n] * sc
// mma.sync m16n8k8 tf32, cp.async double-buffered, 128x128 tile, 256-n slices.
// grid = (36 pairs, 8 splits), 256 threads (8 warps as 4x2, warp tile 32x64).
// ---------------------------------------------------------------------------
#define B_RPAD  36                      // 32-float rows padded to 36 (16B-aligned)
#define B_BUFSZ (2 * 128 * B_RPAD)      // floats per (A,B) buffer pair
#define B_SMEMSZ (2 * B_BUFSZ * 4)      // 73728 bytes (double buffered)
#define B_NCH   8                       // 256 n per CTA / 32 per chunk

__global__ void __launch_bounds__(256, 2) kernelB_mma() {
    extern __shared__ float sm[];

    const int tid = threadIdx.x;
    const int wid = tid >> 5;
    const int lid = tid & 31;
    const int g   = lid >> 2;
    const int t4  = lid & 3;

    int tr, tc; pair_from_idx(blockIdx.x, tr, tc);
    const int i0 = tr * 128, l0 = tc * 128;
    const bool diag = (tr == tc);
    const int ops  = diag ? 1 : 2;
    const int nb   = blockIdx.y * (N_OBS / NSPLIT);

    const uint32_t sbase = smem_u32(sm);
    const int wr = wid & 3;            // i offset wr*32
    const int wc = wid >> 2;           // l offset wc*64
    const int ibase = wr * 32, lbase = wc * 64;

    float c[2][8][4];
    #pragma unroll
    for (int mi = 0; mi < 2; mi++)
        #pragma unroll
        for (int ni = 0; ni < 8; ni++)
            #pragma unroll
            for (int t = 0; t < 4; t++) c[mi][ni][t] = 0.f;

    auto stage = [&](int ch, int buf) {
        const int n0 = nb + ch * 32;
        const int tot = ops << 10;                       // 1024 cp.async per operand
        for (int e = tid; e < tot; e += 256) {
            const int op  = e >> 10;
            const int idx = e & 1023;
            const int row = idx >> 3;
            const int f4  = idx & 7;
            const int grow = (op ? l0 : i0) + row;
            cp_async16(sbase + (uint32_t)((((buf * 2 + op) * 128 + row) * B_RPAD + f4 * 4) * 4),
                       &g_sT[(size_t)grow * N_OBS + n0 + f4 * 4]);
        }
    };

    stage(0, 0);
    CP_COMMIT();

    for (int ch = 0; ch < B_NCH; ch++) {
        const int buf = ch & 1;
        if (ch + 1 < B_NCH) { stage(ch + 1, buf ^ 1); CP_COMMIT(); CP_WAIT1(); }
        else                { CP_WAIT0(); }
        __syncthreads();                                 // buf[ch&1] visible to all

        const uint32_t* SA = (const uint32_t*)(sm + buf * B_BUFSZ);
        const uint32_t* SB = diag ? SA : SA + 128 * B_RPAD;

        #pragma unroll
        for (int ks = 0; ks < 4; ks++) {
            const int kb = ks * 8 + t4;
            uint32_t a[2][4];
            #pragma unroll
            for (int mi = 0; mi < 2; mi++) {
                const int r = (ibase + 16 * mi + g) * B_RPAD;
                a[mi][0] = SA[r + kb];
                a[mi][1] = SA[r + 8 * B_RPAD + kb];
                a[mi][2] = SA[r + kb + 4];
                a[mi][3] = SA[r + 8 * B_RPAD + kb + 4];
            }
            uint32_t bfr[8][2];
            #pragma unroll
            for (int ni = 0; ni < 8; ni++) {
                const int r = (lbase + 8 * ni + g) * B_RPAD;
                bfr[ni][0] = SB[r + kb];
                bfr[ni][1] = SB[r + kb + 4];
            }
            #pragma unroll
            for (int mi = 0; mi < 2; mi++)
                #pragma unroll
                for (int ni = 0; ni < 8; ni++)
                    mma_tf32(c[mi][ni], a[mi], bfr[ni]);
        }
        __syncthreads();                                 // all reads done before buf reuse
    }

    // Epilogue: scale + store partial tile (float2 per fragment row)
    const float sc = (2.0f / (float)KH) / (float)N_OBS;
    float* dst = &g_Mp[((size_t)blockIdx.y * NPAIR + blockIdx.x) * (128 * 128)];
    #pragma unroll
    for (int mi = 0; mi < 2; mi++) {
        const int rr = ibase + 16 * mi + g;
        #pragma unroll
        for (int ni = 0; ni < 8; ni++) {
            const int cc = lbase + 8 * ni + 2 * t4;
            float2 v0 = make_float2(c[mi][ni][0] * sc, c[mi][ni][1] * sc);
            float2 v1 = make_float2(c[mi][ni][2] * sc, c[mi][ni][3] * sc);
            *(float2*)&dst[(size_t)rr * 128 + cc]       = v0;
            *(float2*)&dst[(size_t)(rr + 8) * 128 + cc] = v1;
        }
    }
}

// ---------------------------------------------------------------------------
// Kernel R: reduce 8 split-partials, write M tile + mirrored tile.
// grid = 36 tiles * 4 row-quarters, 256 threads.
// ---------------------------------------------------------------------------
__global__ void __launch_bounds__(256) kernelR() {
    __shared__ float ts[32][133];

    const int tid  = threadIdx.x;
    const int tile = blockIdx.x >> 2;
    const int q    = blockIdx.x & 3;
    int tr, tc; pair_from_idx(tile, tr, tc);
    const int i0 = tr * 128 + q * 32;
    const int l0 = tc * 128;

    for (int e = tid; e < 32 * 128; e += 256) {
        const int r = e >> 7, c = e & 127;
        float v = 0.f;
        #pragma unroll
        for (int s = 0; s < NSPLIT; s++)
            v += g_Mp[((size_t)s * NPAIR + tile) * (128 * 128) + (size_t)(q * 32 + r) * 128 + c];
        ts[r][c] = v;
    }
    __syncthreads();

    for (int e = tid; e < 32 * 128; e += 256) {
        const int r = e >> 7, c = e & 127;
        g_M[(size_t)(i0 + r) * KH + l0 + c] = ts[r][c];
    }
    if (tr != tc) {
        for (int e = tid; e < 128 * 32; e += 256) {
            const int lr = e >> 5, kc = e & 31;
            g_M[(size_t)(l0 + lr) * KH + i0 + kc] = ts[kc][lr];
        }
    }
}

// ---------------------------------------------------------------------------
// Kernel C: A[d,k,l] = M[k,l] * w[k,d] * w[l,d]  (256 MB store-bound)
// grid = (KH/128, KH/8), 256 threads. w staged in 2 d-halves (23 KB smem
// -> 8 CTAs/SM). Streaming stores.
// ---------------------------------------------------------------------------
#define C_KT 8
#define C_LT 128
#define C_WPAD 132

__global__ void __launch_bounds__(256) kernelC(const float* __restrict__ w,
                                               float* __restrict__ out) {
    __shared__ float wld[32][C_WPAD];     // 16.9 KB (one d-half at a time)
    __shared__ float Ms[C_KT][C_LT];      // 4 KB
    __shared__ float wks[DIN][C_KT + 1];  // 2.3 KB

    const int tid = threadIdx.x;
    const int l0  = blockIdx.x * C_LT;
    const int k0  = blockIdx.y * C_KT;

    for (int i = tid; i < C_KT * C_LT; i += 256) {
        const int kk = i >> 7, li = i & 127;
        Ms[kk][li] = g_M[(size_t)(k0 + kk) * KH + l0 + li];
    }
    for (int i = tid; i < C_KT * DIN; i += 256) {
        const int kk = i >> 6, d = i & 63;
        wks[d][kk] = w[(size_t)(k0 + kk) * DIN + d];
    }

    const int j     = tid >> 5;
    const int lane4 = (tid & 31) * 4;

    float4 M4;
    const size_t base = (size_t)(k0 + j) * KH + l0 + lane4;

    #pragma unroll
    for (int h = 0; h < 2; h++) {
        __syncthreads();
        for (int i = tid; i < 32 * C_LT; i += 256) {
            const int li = i >> 5, d = i & 31;
            wld[d][li] = w[(size_t)(l0 + li) * DIN + h * 32 + d];   // coalesced
        }
        __syncthreads();
        if (h == 0) M4 = *(const float4*)&Ms[j][lane4];

        #pragma unroll 8
        for (int dd = 0; dd < 32; dd++) {
            const int d = h * 32 + dd;
            const float wk  = wks[d][j];
            const float4 wl = *(const float4*)&wld[dd][lane4];
            float4 o;
            o.x = (M4.x * wk) * wl.x;
            o.y = (M4.y * wk) * wl.y;
            o.z = (M4.z * wk) * wl.z;
            o.w = (M4.w * wk) * wl.w;
            __stcs((float4*)&out[(size_t)d * (size_t)(KH * KH) + base], o);
        }
    }
}

// ---------------------------------------------------------------------------
extern "C" void kernel_launch(void* const* d_in, const int* in_sizes, int n_in,
                              void* d_out, int out_size) {
    (void)in_sizes; (void)n_in; (void)out_size;
    const float* x = (const float*)d_in[0];
    const float* w = (const float*)d_in[1];
    const float* b = (const float*)d_in[2];
    float* out = (float*)d_out;

    cudaFuncSetAttribute(kernelB_mma, cudaFuncAttributeMaxDynamicSharedMemorySize, B_SMEMSZ);

    kernelA<<<dim3(KH / A_KT, N_OBS / A_NC), 256>>>(x, w, b);
    kernelB_mma<<<dim3(NPAIR, NSPLIT), 256, B_SMEMSZ>>>();
    kernelR<<<NPAIR * 4, 256>>>();
    kernelC<<<dim3(KH / C_LT, KH / C_KT), 256>>>(w, out);
}

// round 5
// speedup vs baseline: 3.9406x; 1.0818x over previous
#include <cuda_runtime.h>
#include <cuda_fp16.h>
#include <cstdint>

#define N_OBS 2048
#define KH    1024
#define DIN   64
#define NTILE 8          // KH / 128
#define NPAIR 36         // upper-triangle tile pairs
#define NSPLIT 8         // split-K factor for kernelB

// Scratch (device globals: allocation-free per harness rules)
__device__ __half g_sT[KH * N_OBS];                  // 4 MB: sin activations fp16, (k, n)
__device__ float  g_M[KH * KH];                      // 4 MB: full symmetric Gram
__device__ float  g_Mp[NSPLIT * NPAIR * 128 * 128];  // 18.9 MB: per-(split,tile) partials

// ---------------------------------------------------------------------------
// Helpers (compute_103-portable: sm_80-class features only)
// ---------------------------------------------------------------------------
__device__ __forceinline__ void pair_from_idx(int idx, int& tr, int& tc) {
    int t = 0, rem = idx;
    while (rem >= NTILE - t) { rem -= NTILE - t; t++; }
    tr = t; tc = t + rem;
}
__device__ __forceinline__ uint32_t smem_u32(const void* p) {
    uint32_t a;
    asm("{ .reg .u64 t; cvta.to.shared.u64 t, %1; cvt.u32.u64 %0, t; }" : "=r"(a) : "l"(p));
    return a;
}
__device__ __forceinline__ void cp_async16(uint32_t dst, const void* src) {
    asm volatile("cp.async.cg.shared.global [%0], [%1], 16;" :: "r"(dst), "l"(src));
}
#define CP_COMMIT() asm volatile("cp.async.commit_group;" ::: "memory")
#define CP_WAIT1()  asm volatile("cp.async.wait_group 1;" ::: "memory")
#define CP_WAIT0()  asm volatile("cp.async.wait_group 0;" ::: "memory")

__device__ __forceinline__ void ldmatrix_x4(uint32_t* r, uint32_t addr) {
    asm volatile("ldmatrix.sync.aligned.m8n8.x4.shared.b16 {%0,%1,%2,%3}, [%4];"
                 : "=r"(r[0]), "=r"(r[1]), "=r"(r[2]), "=r"(r[3]) : "r"(addr));
}
// mma m16n8k16 fp16 in, fp32 accumulate
__device__ __forceinline__ void mma_f16(float* c, const uint32_t* a, const uint32_t* b) {
    asm volatile(
        "mma.sync.aligned.m16n8k16.row.col.f32.f16.f16.f32 "
        "{%0,%1,%2,%3}, {%4,%5,%6,%7}, {%8,%9}, {%0,%1,%2,%3};"
        : "+f"(c[0]), "+f"(c[1]), "+f"(c[2]), "+f"(c[3])
        : "r"(a[0]), "r"(a[1]), "r"(a[2]), "r"(a[3]), "r"(b[0]), "r"(b[1]));
}

// ---------------------------------------------------------------------------
// Kernel A: g_sT[k][n] = half( __sinf( dot(x[n,:], w[k,:]) + b[k] ) )
// grid = (KH/32, N_OBS/128), 256 threads. Warp: 4 k-rows x 128 n.
// ---------------------------------------------------------------------------
#define A_KT 32
#define A_NC 128
#define A_XPAD 132

__global__ void __launch_bounds__(256) kernelA(const float* __restrict__ x,
                                               const float* __restrict__ w,
                                               const float* __restrict__ b) {
    __shared__ float xsT[DIN][A_XPAD];      // 33.8 KB  xsT[d][n_local]
    __shared__ float wks[A_KT][DIN];        // 8 KB

    const int tid = threadIdx.x;
    const int k0  = blockIdx.x * A_KT;
    const int n0  = blockIdx.y * A_NC;

    for (int i = tid; i < A_NC * DIN; i += 256) {
        const int n = i >> 6, d = i & 63;
        xsT[d][n] = x[(size_t)(n0 + n) * DIN + d];      // coalesced read
    }
    for (int i = tid; i < A_KT * DIN; i += 256) {
        const int k = i >> 6, d = i & 63;
        wks[k][d] = w[(size_t)(k0 + k) * DIN + d];
    }
    __syncthreads();

    const int warp  = tid >> 5;
    const int lane4 = (tid & 31) * 4;
    const int r0 = warp * 4;

    float acc[4][4];
    #pragma unroll
    for (int r = 0; r < 4; r++)
        #pragma unroll
        for (int c = 0; c < 4; c++) acc[r][c] = 0.f;

    #pragma unroll 8
    for (int d = 0; d < DIN; d++) {
        const float4 xv = *(const float4*)&xsT[d][lane4];   // LDS.128 conflict-free
        #pragma unroll
        for (int r = 0; r < 4; r++) {
            const float wv = wks[r0 + r][d];                // broadcast
            acc[r][0] += wv * xv.x; acc[r][1] += wv * xv.y;
            acc[r][2] += wv * xv.z; acc[r][3] += wv * xv.w;
        }
    }

    #pragma unroll
    for (int r = 0; r < 4; r++) {
        const float bv = b[k0 + r0 + r];
        __half2 p0 = __floats2half2_rn(__sinf(acc[r][0] + bv), __sinf(acc[r][1] + bv));
        __half2 p1 = __floats2half2_rn(__sinf(acc[r][2] + bv), __sinf(acc[r][3] + bv));
        uint2 u;
        u.x = *(uint32_t*)&p0;
        u.y = *(uint32_t*)&p1;
        *(uint2*)&g_sT[(size_t)(k0 + r0 + r) * N_OBS + n0 + lane4] = u;   // 8B store
    }
}

// ---------------------------------------------------------------------------
// Kernel B: partial Gram via fp16 mma.m16n8k16 + ldmatrix, cp.async dbl-buffer.
// grid = (36 pairs, 8 splits), 256 threads (8 warps 4x2, warp tile 32x64).
// Chunk = 32 n (64B/row). Row stride 80B -> conflict-free ldmatrix.
// ---------------------------------------------------------------------------
#define B_ROWB  80                    // 64B data + 16B pad
#define B_OPB   (128 * B_ROWB)        // 10240 B per operand tile
#define B_BUF   (2 * B_OPB)           // one (A,B) buffer pair
#define B_SMEMB (2 * B_BUF)           // 40960 B double-buffered
#define B_NCH   8                     // 256 n per CTA / 32 per chunk

__global__ void __launch_bounds__(256) kernelB_f16() {
    __shared__ __align__(16) char sm[B_SMEMB];

    const int tid = threadIdx.x;
    const int wid = tid >> 5;
    const int lid = tid & 31;
    const int g   = lid >> 2;
    const int t4  = lid & 3;

    int tr, tc; pair_from_idx(blockIdx.x, tr, tc);
    const int i0 = tr * 128, l0 = tc * 128;
    const bool diag = (tr == tc);
    const int ops  = diag ? 1 : 2;
    const int nb   = blockIdx.y * (N_OBS / NSPLIT);

    const uint32_t sb = smem_u32(sm);
    const int wr = wid & 3;            // i offset wr*32
    const int wc = wid >> 2;           // l offset wc*64
    const int ibase = wr * 32, lbase = wc * 64;

    float c[2][8][4];
    #pragma unroll
    for (int mi = 0; mi < 2; mi++)
        #pragma unroll
        for (int ni = 0; ni < 8; ni++)
            #pragma unroll
            for (int t = 0; t < 4; t++) c[mi][ni][t] = 0.f;

    auto stage = [&](int ch, int buf) {
        const int n0 = nb + ch * 32;
        const int tot = ops << 9;                        // 512 cp.async per operand
        for (int e = tid; e < tot; e += 256) {
            const int op  = e >> 9;
            const int idx = e & 511;
            const int row = idx >> 2;
            const int c16 = idx & 3;
            const int grow = (op ? l0 : i0) + row;
            cp_async16(sb + (uint32_t)(buf * B_BUF + op * B_OPB + row * B_ROWB + c16 * 16),
                       &g_sT[(size_t)grow * N_OBS + n0 + c16 * 8]);
        }
    };

    // per-lane ldmatrix address offsets (within an operand tile)
    const uint32_t aOff0 = (uint32_t)((ibase + (lid & 15)) * B_ROWB + (lid >> 4) * 16);
    const uint32_t bRow  = (uint32_t)(lbase + ((lid >> 4) << 3) + (lid & 7));
    const uint32_t bOff0 = bRow * B_ROWB + ((lid >> 3) & 1) * 16;

    stage(0, 0);
    CP_COMMIT();

    for (int ch = 0; ch < B_NCH; ch++) {
        const int buf = ch & 1;
        if (ch + 1 < B_NCH) { stage(ch + 1, buf ^ 1); CP_COMMIT(); CP_WAIT1(); }
        else                { CP_WAIT0(); }
        __syncthreads();

        const uint32_t aBase = sb + buf * B_BUF;
        const uint32_t bBase = diag ? aBase : aBase + B_OPB;

        #pragma unroll
        for (int ks = 0; ks < 2; ks++) {                 // two k16 steps per 32-n chunk
            uint32_t a[2][4];
            #pragma unroll
            for (int mi = 0; mi < 2; mi++)
                ldmatrix_x4(a[mi], aBase + aOff0 + (uint32_t)(mi * 16 * B_ROWB + ks * 32));
            uint32_t bb[4][4];
            #pragma unroll
            for (int p = 0; p < 4; p++)
                ldmatrix_x4(bb[p], bBase + bOff0 + (uint32_t)(p * 16 * B_ROWB + ks * 32));
            #pragma unroll
            for (int mi = 0; mi < 2; mi++)
                #pragma unroll
                for (int ni = 0; ni < 8; ni++)
                    mma_f16(c[mi][ni], a[mi], &bb[ni >> 1][(ni & 1) * 2]);
        }
        __syncthreads();                                 // reads done before buf reuse
    }

    // Epilogue: scale + store partial tile
    const float sc = (2.0f / (float)KH) / (float)N_OBS;
    float* dst = &g_Mp[((size_t)blockIdx.y * NPAIR + blockIdx.x) * (128 * 128)];
    #pragma unroll
    for (int mi = 0; mi < 2; mi++) {
        const int rr = ibase + 16 * mi + g;
        #pragma unroll
        for (int ni = 0; ni < 8; ni++) {
            const int cc = lbase + 8 * ni + 2 * t4;
            float2 v0 = make_float2(c[mi][ni][0] * sc, c[mi][ni][1] * sc);
            float2 v1 = make_float2(c[mi][ni][2] * sc, c[mi][ni][3] * sc);
            *(float2*)&dst[(size_t)rr * 128 + cc]       = v0;
            *(float2*)&dst[(size_t)(rr + 8) * 128 + cc] = v1;
        }
    }
}

// ---------------------------------------------------------------------------
// Kernel R: reduce 8 split-partials, write M tile + mirrored tile.
// grid = 36 tiles * 4 row-quarters, 256 threads.
// ---------------------------------------------------------------------------
__global__ void __launch_bounds__(256) kernelR() {
    __shared__ float ts[32][133];

    const int tid  = threadIdx.x;
    const int tile = blockIdx.x >> 2;
    const int q    = blockIdx.x & 3;
    int tr, tc; pair_from_idx(tile, tr, tc);
    const int i0 = tr * 128 + q * 32;
    const int l0 = tc * 128;

    for (int e = tid; e < 32 * 128; e += 256) {
        const int r = e >> 7, c = e & 127;
        float v = 0.f;
        #pragma unroll
        for (int s = 0; s < NSPLIT; s++)
            v += g_Mp[((size_t)s * NPAIR + tile) * (128 * 128) + (size_t)(q * 32 + r) * 128 + c];
        ts[r][c] = v;
    }
    __syncthreads();

    for (int e = tid; e < 32 * 128; e += 256) {
        const int r = e >> 7, c = e & 127;
        g_M[(size_t)(i0 + r) * KH + l0 + c] = ts[r][c];
    }
    if (tr != tc) {
        for (int e = tid; e < 128 * 32; e += 256) {
            const int lr = e >> 5, kc = e & 31;
            g_M[(size_t)(l0 + lr) * KH + i0 + kc] = ts[kc][lr];
        }
    }
}

// ---------------------------------------------------------------------------
// Kernel C: A[d,k,l] = M[k,l] * w[k,d] * w[l,d]  (256 MB store-bound)
// grid = (KH/128, KH/8), 256 threads. Forced 8 CTAs/SM for store concurrency.
// ---------------------------------------------------------------------------
#define C_KT 8
#define C_LT 128
#define C_WPAD 132

__global__ void __launch_bounds__(256, 8) kernelC(const float* __restrict__ w,
                                                  float* __restrict__ out) {
    __shared__ float wld[32][C_WPAD];     // 16.9 KB (one d-half at a time)
    __shared__ float Ms[C_KT][C_LT];      // 4 KB
    __shared__ float wks[DIN][C_KT + 1];  // 2.3 KB

    const int tid = threadIdx.x;
    const int l0  = blockIdx.x * C_LT;
    const int k0  = blockIdx.y * C_KT;

    for (int i = tid; i < C_KT * C_LT; i += 256) {
        const int kk = i >> 7, li = i & 127;
        Ms[kk][li] = g_M[(size_t)(k0 + kk) * KH + l0 + li];
    }
    for (int i = tid; i < C_KT * DIN; i += 256) {
        const int kk = i >> 6, d = i & 63;
        wks[d][kk] = w[(size_t)(k0 + kk) * DIN + d];
    }

    const int j     = tid >> 5;
    const int lane4 = (tid & 31) * 4;

    float4 M4;
    const size_t base = (size_t)(k0 + j) * KH + l0 + lane4;

    #pragma unroll
    for (int h = 0; h < 2; h++) {
        __syncthreads();
        for (int i = tid; i < 32 * C_LT; i += 256) {
            const int li = i >> 5, d = i & 31;
            wld[d][li] = w[(size_t)(l0 + li) * DIN + h * 32 + d];   // coalesced
        }
        __syncthreads();
        if (h == 0) M4 = *(const float4*)&Ms[j][lane4];

        #pragma unroll 8
        for (int dd = 0; dd < 32; dd++) {
            const int d = h * 32 + dd;
            const float wk  = wks[d][j];
            const float4 wl = *(const float4*)&wld[dd][lane4];
            float4 o;
            o.x = (M4.x * wk) * wl.x;
            o.y = (M4.y * wk) * wl.y;
            o.z = (M4.z * wk) * wl.z;
            o.w = (M4.w * wk) * wl.w;
            __stcs((float4*)&out[(size_t)d * (size_t)(KH * KH) + base], o);
        }
    }
}

// ---------------------------------------------------------------------------
extern "C" void kernel_launch(void* const* d_in, const int* in_sizes, int n_in,
                              void* d_out, int out_size) {
    (void)in_sizes; (void)n_in; (void)out_size;
    const float* x = (const float*)d_in[0];
    const float* w = (const float*)d_in[1];
    const float* b = (const float*)d_in[2];
    float* out = (float*)d_out;

    kernelA<<<dim3(KH / A_KT, N_OBS / A_NC), 256>>>(x, w, b);
    kernelB_f16<<<dim3(NPAIR, NSPLIT), 256>>>();
    kernelR<<<NPAIR * 4, 256>>>();
    kernelC<<<dim3(KH / C_LT, KH / C_KT), 256>>>(w, out);
}